// round 17
// baseline (speedup 1.0000x reference)
#include <cuda_runtime.h>
#include <cuda_fp16.h>
#include <cstdint>
#include <math.h>

#define BB 8
#define LL 1024
#define CC 768
#define NH 12
#define HD 64
#define M_TOT (BB*LL)      /* 8192 */
#define NQKV (3*CC)        /* 2304 */
#define NQK  (2*CC)        /* 1536 */

// ---------------- scratch (device globals: no allocation allowed) ----------
__device__ __half g_xh[(size_t)M_TOT * CC];
__device__ __half g_wqh[(size_t)NQKV * CC];
__device__ __half g_woh[(size_t)CC * CC];
__device__ __half g_aoh[(size_t)M_TOT * CC];
__device__ __half g_qh[(size_t)BB*NH*LL*HD];
__device__ __half g_kh[(size_t)BB*NH*LL*HD];
__device__ __half g_vh[(size_t)BB*NH*LL*HD];

// ---------------------------------------------------------------------------
__device__ __forceinline__ float ex2f(float x) {
    float y;
    asm("ex2.approx.ftz.f32 %0, %1;" : "=f"(y) : "f"(x));
    return y;
}
__device__ __forceinline__ uint32_t smem_u32(const void* p) {
    uint32_t a;
    asm("{ .reg .u64 t; cvta.to.shared.u64 t, %1; cvt.u32.u64 %0, t; }"
        : "=r"(a) : "l"(p));
    return a;
}
__device__ __forceinline__ uint32_t pack2h(float a, float b) {
    __half2 v = __floats2half2_rn(a, b);
    return *(uint32_t*)&v;
}

#define MMA_F16(Cr, A0, A1, A2, A3, B0, B1) \
    asm volatile("mma.sync.aligned.m16n8k16.row.col.f32.f16.f16.f32 " \
        "{%0,%1,%2,%3}, {%4,%5,%6,%7}, {%8,%9}, {%0,%1,%2,%3};" \
        : "+f"((Cr)[0]), "+f"((Cr)[1]), "+f"((Cr)[2]), "+f"((Cr)[3]) \
        : "r"(A0), "r"(A1), "r"(A2), "r"(A3), "r"(B0), "r"(B1))

#define LDSM_X4(r0, r1, r2, r3, addr) \
    asm volatile("ldmatrix.sync.aligned.m8n8.x4.shared.b16 {%0,%1,%2,%3}, [%4];" \
        : "=r"(r0), "=r"(r1), "=r"(r2), "=r"(r3) : "r"(addr))

#define LDSM_X4_T(r0, r1, r2, r3, addr) \
    asm volatile("ldmatrix.sync.aligned.m8n8.x4.trans.shared.b16 {%0,%1,%2,%3}, [%4];" \
        : "=r"(r0), "=r"(r1), "=r"(r2), "=r"(r3) : "r"(addr))

#define CP_ASYNC16(dst, src) \
    asm volatile("cp.async.cg.shared.global [%0], [%1], 16;" \
                 :: "r"(dst), "l"(src) : "memory")
#define CP_COMMIT() asm volatile("cp.async.commit_group;" ::: "memory")
#define CP_WAIT0()  asm volatile("cp.async.wait_group 0;" ::: "memory")
#define CP_WAIT1()  asm volatile("cp.async.wait_group 1;" ::: "memory")

// ===========================================================================
// merged prep: fp32 -> fp16 over three arrays in one launch
// ===========================================================================
__global__ __launch_bounds__(256) void cvt3_kernel(
    const float* __restrict__ s0, __half* __restrict__ h0, int n0,
    const float* __restrict__ s1, __half* __restrict__ h1, int n1,
    const float* __restrict__ s2, __half* __restrict__ h2, int n2)
{
    int i = blockIdx.x * 256 + threadIdx.x;
    const float* s; __half* h;
    if (i < n0)           { s = s0;  h = h0; }
    else if (i < n0 + n1) { i -= n0; s = s1; h = h1; }
    else                  { i -= n0 + n1; if (i >= n2) return; s = s2; h = h2; }
    float4 v = ((const float4*)s)[i];
    ((__half2*)h)[2*i]   = __floats2half2_rn(v.x, v.y);
    ((__half2*)h)[2*i+1] = __floats2half2_rn(v.z, v.w);
}

// ===========================================================================
// Pipelined fp16 1-term GEMM (NT), BK=32, 2-stage, 3 CTAs/SM target.
// mode 0: plain fp32 C epilogue (out-proj).
// mode 1: QKV — col0 >= NQK: V-direct fp16 [b,h,l,e];
//                col0 <  NQK: fused RMSNorm+RoPE epilogue -> g_qh/g_kh.
// Stage (20480B): A@0 (128x80B), B@10240. 2 stages = 40960B dyn smem.
// ===========================================================================
#define GSTG 20480

__global__ __launch_bounds__(256, 3) void gemm_1t_kernel(
    const __half* __restrict__ Ah, const __half* __restrict__ Bh,
    float* __restrict__ C, int mode, int M, int N, int K,
    const float* __restrict__ qg, const float* __restrict__ kg)
{
    extern __shared__ uint8_t smraw[];
    const uint32_t sbase = smem_u32(smraw);

    const int tid  = threadIdx.x;
    const int wid  = tid >> 5;
    const int lane = tid & 31;
    const int wm = wid & 1;
    const int wn = wid >> 1;
    const int row0 = blockIdx.y * 128;
    const int col0 = blockIdx.x * 128;
    const int q4 = lane >> 2;
    const int l3 = lane & 3;
    const int lr16  = lane & 15;
    const int lhalf = (lane >> 4) * 16;

    float c[4][4][4];
#pragma unroll
    for (int m = 0; m < 4; m++)
#pragma unroll
        for (int n = 0; n < 4; n++)
#pragma unroll
            for (int q = 0; q < 4; q++) c[m][n][q] = 0.f;

    const int nch = K / 32;

    // prologue: chunk 0 into stage 0
#pragma unroll
    for (int j = 0; j < 4; j++) {
        int i = tid + 256 * j;
        int a = i >> 9, r = (i >> 2) & 127, cc = i & 3;
        const __half* base = (a == 0) ? Ah : Bh;
        int grow = ((a == 0) ? row0 : col0) + r;
        CP_ASYNC16(sbase + a * 10240 + r * 80 + cc * 16,
                   base + (size_t)grow * K + cc * 8);
    }
    CP_COMMIT();

#pragma unroll 1
    for (int ch = 0; ch < nch; ch++) {
        if (ch + 1 < nch) {
            uint32_t dst = sbase + ((ch + 1) & 1) * GSTG;
            const int k0 = (ch + 1) * 32;
#pragma unroll
            for (int j = 0; j < 4; j++) {
                int i = tid + 256 * j;
                int a = i >> 9, r = (i >> 2) & 127, cc = i & 3;
                const __half* base = (a == 0) ? Ah : Bh;
                int grow = ((a == 0) ? row0 : col0) + r;
                CP_ASYNC16(dst + a * 10240 + r * 80 + cc * 16,
                           base + (size_t)grow * K + k0 + cc * 8);
            }
            CP_COMMIT();
            CP_WAIT1();
        } else {
            CP_WAIT0();
        }
        __syncthreads();

        const uint32_t sst = sbase + (ch & 1) * GSTG;

#pragma unroll
        for (int ks = 0; ks < 2; ks++) {
            uint32_t ah[4][4];
#pragma unroll
            for (int m = 0; m < 4; m++) {
                uint32_t arow = sst + (wm * 64 + m * 16 + lr16) * 80 + lhalf + ks * 32;
                LDSM_X4(ah[m][0], ah[m][1], ah[m][2], ah[m][3], arow);
            }
#pragma unroll
            for (int np = 0; np < 2; np++) {
                uint32_t brow = sst + 10240 + (wn * 32 + np * 16 + lr16) * 80 + lhalf + ks * 32;
                uint32_t h0, h1, h2, h3;
                LDSM_X4(h0, h1, h2, h3, brow);
#pragma unroll
                for (int m = 0; m < 4; m++)
                    MMA_F16(c[m][2*np],   ah[m][0], ah[m][1], ah[m][2], ah[m][3], h0, h2);
#pragma unroll
                for (int m = 0; m < 4; m++)
                    MMA_F16(c[m][2*np+1], ah[m][0], ah[m][1], ah[m][2], ah[m][3], h1, h3);
            }
        }
        __syncthreads();
    }

    if (mode == 0) {
#pragma unroll
        for (int m = 0; m < 4; m++) {
            const int r = row0 + wm * 64 + m * 16 + q4;
#pragma unroll
            for (int n = 0; n < 4; n++) {
                const int cc = col0 + wn * 32 + n * 8 + l3 * 2;
                *(float2*)(C + (size_t)r * N + cc)       = make_float2(c[m][n][0], c[m][n][1]);
                *(float2*)(C + (size_t)(r + 8) * N + cc) = make_float2(c[m][n][2], c[m][n][3]);
            }
        }
        return;
    }

    if (col0 >= NQK) {
        // V-direct: fp16 [b, h, l, e]
#pragma unroll
        for (int m = 0; m < 4; m++) {
            const int r = row0 + wm * 64 + m * 16 + q4;
            const int bi = r >> 10;
            const int li = r & 1023;
#pragma unroll
            for (int n = 0; n < 4; n++) {
                const int vc = col0 + wn * 32 + n * 8 + l3 * 2 - NQK;
                const int hh = vc >> 6, ee = vc & 63;
                size_t base = ((size_t)(bi * NH + hh) * LL + li) * HD + ee;
                *(__half2*)&g_vh[base]          = __floats2half2_rn(c[m][n][0], c[m][n][1]);
                *(__half2*)&g_vh[base + 8 * HD] = __floats2half2_rn(c[m][n][2], c[m][n][3]);
            }
        }
        return;
    }

    // ---- fused RMSNorm + RoPE epilogue (Q/K columns) ----
    // Stage fp32 accumulators to smem. 128 rows x 132 floats needs 67.6KB;
    // the 40.96KB pipeline region is too small, so stage in two 64-row halves.
    float* sf = (float*)smraw;
    const float ifr = exp2f(-13.287712379549449f * (float)lane * (1.0f / 32.0f));
    const float QS = 0.125f * 1.4426950408889634f;
    const bool isQ = (col0 < CC);
    const float g1 = isQ ? qg[lane]      : kg[lane];
    const float g2 = isQ ? qg[lane + 32] : kg[lane + 32];
    const int hbase = (isQ ? col0 : col0 - CC) >> 6;

#pragma unroll
    for (int half128 = 0; half128 < 2; half128++) {   // rows [0,64) then [64,128)
        __syncthreads();
        if (wm == half128) {
#pragma unroll
            for (int m = 0; m < 4; m++) {
                const int rr = m * 16 + q4;            // 0..63 within half
#pragma unroll
                for (int n = 0; n < 4; n++) {
                    const int cc = wn * 32 + n * 8 + l3 * 2;
                    *(float2*)&sf[rr * 132 + cc]       = make_float2(c[m][n][0], c[m][n][1]);
                    *(float2*)&sf[(rr + 8) * 132 + cc] = make_float2(c[m][n][2], c[m][n][3]);
                }
            }
        }
        __syncthreads();

        // 128 warp-tasks: 64 rows x 2 column-halves, 16 tasks per warp
#pragma unroll 4
        for (int t = 0; t < 16; t++) {
            const int task = wid * 16 + t;      // 0..127
            const int row  = task & 63;
            const int half64 = task >> 6;       // 0 or 1
            const int gr = row0 + half128 * 64 + row;
            const int bi = gr >> 10, li = gr & 1023;

            float x1 = sf[row * 132 + half64 * 64 + lane];
            float x2 = sf[row * 132 + half64 * 64 + lane + 32];
            float ss = x1 * x1 + x2 * x2;
#pragma unroll
            for (int o = 16; o; o >>= 1) ss += __shfl_xor_sync(0xffffffffu, ss, o);
            float r = rsqrtf(ss * (1.0f / HD) + 1e-6f);

            float ang = (float)li * ifr;
            float cs = __cosf(ang), sn = __sinf(ang);
            float n1 = x1 * r * g1, n2 = x2 * r * g2;
            float o1 = n1 * cs - n2 * sn;
            float o2 = n1 * sn + n2 * cs;

            const int h = hbase + half64;
            const size_t d = ((size_t)(bi * NH + h) * LL + li) * HD;
            if (isQ) {
                g_qh[d + lane]      = __float2half_rn(o1 * QS);
                g_qh[d + lane + 32] = __float2half_rn(o2 * QS);
            } else {
                g_kh[d + lane]      = __float2half_rn(o1);
                g_kh[d + lane + 32] = __float2half_rn(o2);
            }
        }
    }
}

// ===========================================================================
// Flash attention, all single-term fp16 (unchanged core).
// ===========================================================================
#define ASTG  18432
#define AROW  144
#define AROWW 36

__global__ __launch_bounds__(256) void attn_mma_kernel()
{
    extern __shared__ uint8_t smraw[];
    uint32_t* smw = (uint32_t*)smraw;
    const uint32_t sbase = smem_u32(smraw);

    const int tid  = threadIdx.x;
    const int w    = tid >> 5;
    const int lane = tid & 31;
    const int q4   = lane >> 2;
    const int l3   = lane & 3;
    const int qt = blockIdx.x, h = blockIdx.y, b = blockIdx.z;

    const size_t hb = (size_t)(b * NH + h) * LL * HD;
    const __half* Qh = g_qh + hb + (size_t)qt * 128 * HD;
    const __half* Kh = g_kh + hb;
    const __half* Vh = g_vh + hb;

#pragma unroll
    for (int t = 0; t < 4; t++) {
        int i = tid + 256 * t;
        int r = i >> 3, c = i & 7;
        CP_ASYNC16(sbase + r * AROW + c * 16, Qh + (size_t)r * HD + c * 8);
    }
    CP_COMMIT(); CP_WAIT0();
    __syncthreads();

    uint32_t qhf[4][4];
#pragma unroll
    for (int ks = 0; ks < 4; ks++) {
        int base = (w * 16 + q4) * AROWW + ks * 8 + l3;
        qhf[ks][0] = smw[base];       qhf[ks][1] = smw[base + 8 * AROWW];
        qhf[ks][2] = smw[base + 4];   qhf[ks][3] = smw[base + 8 * AROWW + 4];
    }
    __syncthreads();

    float m0 = -1e30f, m1 = -1e30f, ls0 = 0.f, ls1 = 0.f;
    float O[8][4];
#pragma unroll
    for (int n = 0; n < 8; n++)
#pragma unroll
        for (int q = 0; q < 4; q++) O[n][q] = 0.f;

#pragma unroll
    for (int t = 0; t < 4; t++) {
        int i = tid + 256 * t;
        int a = i >> 9, r = (i >> 3) & 63, c = i & 7;
        const __half* base = (a == 0) ? Kh : Vh;
        CP_ASYNC16(sbase + a * 9216 + r * AROW + c * 16,
                   base + (size_t)r * HD + c * 8);
    }
    CP_COMMIT();

#pragma unroll 1
    for (int kt = 0; kt < 16; kt++) {
        if (kt < 15) {
            uint32_t dst = sbase + ((kt + 1) & 1) * ASTG;
            const int r0 = (kt + 1) * 64;
#pragma unroll
            for (int t = 0; t < 4; t++) {
                int i = tid + 256 * t;
                int a = i >> 9, r = (i >> 3) & 63, c = i & 7;
                const __half* base = (a == 0) ? Kh : Vh;
                CP_ASYNC16(dst + a * 9216 + r * AROW + c * 16,
                           base + (size_t)(r0 + r) * HD + c * 8);
            }
            CP_COMMIT();
            CP_WAIT1();
        } else {
            CP_WAIT0();
        }
        __syncthreads();

        const uint32_t* KW = smw + (kt & 1) * (ASTG / 4);
        const uint32_t vbase = sbase + (kt & 1) * ASTG + 9216;

        float S[8][4];
#pragma unroll
        for (int n = 0; n < 8; n++)
#pragma unroll
            for (int q = 0; q < 4; q++) S[n][q] = 0.f;

#pragma unroll
        for (int ks = 0; ks < 4; ks++) {
#pragma unroll
            for (int g = 0; g < 2; g++) {
                uint32_t bh[4][2];
#pragma unroll
                for (int j = 0; j < 4; j++) {
                    int kb = ((g * 4 + j) * 8 + q4) * AROWW + ks * 8 + l3;
                    bh[j][0] = KW[kb];  bh[j][1] = KW[kb + 4];
                }
#pragma unroll
                for (int j = 0; j < 4; j++)
                    MMA_F16(S[g*4+j], qhf[ks][0], qhf[ks][1], qhf[ks][2], qhf[ks][3],
                            bh[j][0], bh[j][1]);
            }
        }

        float mx0 = -1e30f, mx1 = -1e30f;
#pragma unroll
        for (int nt = 0; nt < 8; nt++) {
            mx0 = fmaxf(mx0, fmaxf(S[nt][0], S[nt][1]));
            mx1 = fmaxf(mx1, fmaxf(S[nt][2], S[nt][3]));
        }
        mx0 = fmaxf(mx0, __shfl_xor_sync(0xffffffffu, mx0, 1));
        mx0 = fmaxf(mx0, __shfl_xor_sync(0xffffffffu, mx0, 2));
        mx1 = fmaxf(mx1, __shfl_xor_sync(0xffffffffu, mx1, 1));
        mx1 = fmaxf(mx1, __shfl_xor_sync(0xffffffffu, mx1, 2));
        float mn0 = fmaxf(m0, mx0), mn1 = fmaxf(m1, mx1);
        float a0 = ex2f(m0 - mn0), a1 = ex2f(m1 - mn1);
        float rs0 = 0.f, rs1 = 0.f;
#pragma unroll
        for (int nt = 0; nt < 8; nt++) {
            S[nt][0] = ex2f(S[nt][0] - mn0); S[nt][1] = ex2f(S[nt][1] - mn0);
            S[nt][2] = ex2f(S[nt][2] - mn1); S[nt][3] = ex2f(S[nt][3] - mn1);
            rs0 += S[nt][0] + S[nt][1];
            rs1 += S[nt][2] + S[nt][3];
        }
        rs0 += __shfl_xor_sync(0xffffffffu, rs0, 1);
        rs0 += __shfl_xor_sync(0xffffffffu, rs0, 2);
        rs1 += __shfl_xor_sync(0xffffffffu, rs1, 1);
        rs1 += __shfl_xor_sync(0xffffffffu, rs1, 2);
        ls0 = ls0 * a0 + rs0;  ls1 = ls1 * a1 + rs1;
        m0 = mn0;  m1 = mn1;
#pragma unroll
        for (int nt = 0; nt < 8; nt++) {
            O[nt][0] *= a0; O[nt][1] *= a0;
            O[nt][2] *= a1; O[nt][3] *= a1;
        }

        uint32_t ph[4][4];
#pragma unroll
        for (int j = 0; j < 4; j++) {
            ph[j][0] = pack2h(S[2*j][0],   S[2*j][1]);
            ph[j][1] = pack2h(S[2*j][2],   S[2*j][3]);
            ph[j][2] = pack2h(S[2*j+1][0], S[2*j+1][1]);
            ph[j][3] = pack2h(S[2*j+1][2], S[2*j+1][3]);
        }

        const uint32_t lrow = (lane & 15);
        const uint32_t lcol = ((lane >> 4) & 1) * 16;
#pragma unroll
        for (int j = 0; j < 4; j++) {
            uint32_t va = vbase + (16 * j + lrow) * AROW + lcol;
#pragma unroll
            for (int pp = 0; pp < 2; pp++) {
                uint32_t vh[2][4];
#pragma unroll
                for (int t = 0; t < 2; t++) {
                    uint32_t addr = va + (pp * 2 + t) * 32;
                    LDSM_X4_T(vh[t][0], vh[t][1], vh[t][2], vh[t][3], addr);
                }
#pragma unroll
                for (int t = 0; t < 2; t++) {
                    MMA_F16(O[4*pp+2*t],   ph[j][0], ph[j][1], ph[j][2], ph[j][3],
                            vh[t][0], vh[t][1]);
                    MMA_F16(O[4*pp+2*t+1], ph[j][0], ph[j][1], ph[j][2], ph[j][3],
                            vh[t][2], vh[t][3]);
                }
            }
        }
        __syncthreads();
    }

    const float inv0 = 1.0f / ls0, inv1 = 1.0f / ls1;
    const int row0 = qt * 128 + w * 16 + q4;
    const size_t o0 = ((size_t)b * LL + row0) * CC + h * HD;
    const size_t o1 = o0 + 8 * CC;
#pragma unroll
    for (int nt = 0; nt < 8; nt++) {
        int cc = nt * 8 + 2 * l3;
        *(uint32_t*)(g_aoh + o0 + cc) = pack2h(O[nt][0] * inv0, O[nt][1] * inv0);
        *(uint32_t*)(g_aoh + o1 + cc) = pack2h(O[nt][2] * inv1, O[nt][3] * inv1);
    }
}

// ---------------------------------------------------------------------------
extern "C" void kernel_launch(void* const* d_in, const int* in_sizes, int n_in,
                              void* d_out, int out_size)
{
    const float* x      = (const float*)d_in[0];
    const float* w_qkv  = (const float*)d_in[1];
    const float* qgam   = (const float*)d_in[2];
    const float* kgam   = (const float*)d_in[3];
    const float* w_out  = (const float*)d_in[4];
    float* out = (float*)d_out;

    __half *xh, *wqh, *woh, *aoh;
    cudaGetSymbolAddress((void**)&xh, g_xh);
    cudaGetSymbolAddress((void**)&wqh, g_wqh);
    cudaGetSymbolAddress((void**)&woh, g_woh);
    cudaGetSymbolAddress((void**)&aoh, g_aoh);

    cudaFuncSetAttribute(gemm_1t_kernel,
                         cudaFuncAttributeMaxDynamicSharedMemorySize, 2 * GSTG);
    cudaFuncSetAttribute(attn_mma_kernel,
                         cudaFuncAttributeMaxDynamicSharedMemorySize, 2 * ASTG);

    // 0) prepare all fp16 operands in one launch
    const int n0 = M_TOT * CC / 4, n1 = NQKV * CC / 4, n2 = CC * CC / 4;
    cvt3_kernel<<<(n0 + n1 + n2 + 255) / 256, 256>>>(
        x, xh, n0, w_qkv, wqh, n1, w_out, woh, n2);

    // 1) QKV projection + fused RMSNorm/RoPE (Q/K) + V-direct epilogue
    gemm_1t_kernel<<<dim3(NQKV / 128, M_TOT / 128), 256, 2 * GSTG>>>(
        xh, wqh, nullptr, 1, M_TOT, NQKV, CC, qgam, kgam);

    // 2) Flash attention (all 1-term)
    attn_mma_kernel<<<dim3(LL / 128, NH, BB), 256, 2 * ASTG>>>();

    // 3) Output projection (1-term, fp32 out)
    gemm_1t_kernel<<<dim3(CC / 128, M_TOT / 128), 256, 2 * GSTG>>>(
        aoh, woh, out, 0, M_TOT, CC, CC, nullptr, nullptr);
}